// round 5
// baseline (speedup 1.0000x reference)
#include <cuda_runtime.h>
#include <math.h>

#define TN     1024
#define TRANGE 8.0f                    // table covers x0 in [-8, 8)
#define TSCALE ((float)TN / (2.0f * TRANGE))   // 64
#define TOFFS  ((float)(TN / 2))               // 512

// Constant weights (prescaled): [0:4) w_ih' [4:8) w_hh' [8:12) bias'
// (i,f,o gates scaled by 0.5 to fold into sigmoid; g unscaled)
// [12:30) w_lin  [30] b_lin
__constant__ float c_w[31];

__device__ float  g_stage[31];
__device__ float4 g_tab[TN];   // (h0, c0, dh, dc) as function of x0

__device__ __forceinline__ float tanh_fast(float x) {
    float y;
    asm("tanh.approx.f32 %0, %1;" : "=f"(y) : "f"(x));
    return y;
}
// argument already prescaled by 0.5
__device__ __forceinline__ float sigmoid_pre(float half_x) {
    return fmaf(tanh_fast(half_x), 0.5f, 0.5f);
}

// ---------------- setup: stage weights + build exact step0 table -----------
__device__ __forceinline__ void step0_exact(
    float x, float wi, float wg, float wo, float bi, float bg, float bo,
    float* h0, float* c0)
{
    float i0 = 1.0f / (1.0f + expf(-(fmaf(wi, x, bi))));
    float g0 = tanhf(fmaf(wg, x, bg));
    float o0 = 1.0f / (1.0f + expf(-(fmaf(wo, x, bo))));
    float c  = i0 * g0;
    *c0 = c;
    *h0 = o0 * tanhf(c);
}

__global__ void setup_kernel(const float* __restrict__ w_ih,
                             const float* __restrict__ w_hh,
                             const float* __restrict__ b_ih,
                             const float* __restrict__ b_hh,
                             const float* __restrict__ w_lin,
                             const float* __restrict__ b_lin)
{
    int t = threadIdx.x;
    if (t < 4) {
        float s = (t == 2) ? 1.0f : 0.5f;       // g gate unscaled
        g_stage[t]     = w_ih[t] * s;
        g_stage[4 + t] = w_hh[t] * s;
        g_stage[8 + t] = (b_ih[t] + b_hh[t]) * s;
    } else if (t < 22) {
        g_stage[8 + t] = w_lin[t - 4];          // 12..29
    } else if (t == 22) {
        g_stage[30] = b_lin[0];
    }

    const float wi = w_ih[0], wg = w_ih[2], wo = w_ih[3];
    const float bi = b_ih[0] + b_hh[0];
    const float bg = b_ih[2] + b_hh[2];
    const float bo = b_ih[3] + b_hh[3];
    const float inv = 1.0f / TSCALE;

    for (int i = t; i < TN; i += blockDim.x) {
        float x0 = ((float)i       - TOFFS) * inv;
        float x1 = ((float)(i + 1) - TOFFS) * inv;
        float h0, c0, h1, c1;
        step0_exact(x0, wi, wg, wo, bi, bg, bo, &h0, &c0);
        step0_exact(x1, wi, wg, wo, bi, bg, bo, &h1, &c1);
        g_tab[i] = make_float4(h0, c0, h1 - h0, c1 - c0);
    }
}

// ---------------- main kernel ----------------------------------------------
__global__ __launch_bounds__(256, 8) void lstm_lin_kernel(
    const float* __restrict__ x, float* __restrict__ out, int nrows)
{
    __shared__ float4 stab[TN];
#pragma unroll
    for (int i = threadIdx.x; i < TN; i += 256)
        stab[i] = __ldg(&g_tab[i]);
    __syncthreads();

    const int stride = gridDim.x * 256;

    for (int r = blockIdx.x * 256 + threadIdx.x; r < nrows; r += stride) {
        const float2* p = reinterpret_cast<const float2*>(x) + (size_t)r * 9;
        float v[18];
#pragma unroll
        for (int j = 0; j < 9; j++) {
            float2 t = __ldg(p + j);
            v[2 * j] = t.x; v[2 * j + 1] = t.y;
        }

        float acc = c_w[30];

#pragma unroll
        for (int e = 0; e < 6; e++) {
            const float x0 = v[e * 3 + 0];
            const float x1 = v[e * 3 + 1];
            const float x2 = v[e * 3 + 2];

            // ---- step 0: whole step is a 1-D function of x0 -> table ----
            float t = fmaf(x0, TSCALE, TOFFS);
            t = fminf(fmaxf(t, 0.0f), (float)TN - 0.51f);
            int   i  = (int)t;
            float dx = t - (float)i;
            float4 e4 = stab[i];
            float h = fmaf(dx, e4.z, e4.x);     // h0
            float c = fmaf(dx, e4.w, e4.y);     // c0
            acc = fmaf(h, c_w[12 + e * 3 + 0], acc);

            // ---- step 1 ----
            float i1 = sigmoid_pre(fmaf(c_w[4], h, fmaf(c_w[0], x1, c_w[8])));
            float f1 = sigmoid_pre(fmaf(c_w[5], h, fmaf(c_w[1], x1, c_w[9])));
            float g1 = tanh_fast  (fmaf(c_w[6], h, fmaf(c_w[2], x1, c_w[10])));
            float o1 = sigmoid_pre(fmaf(c_w[7], h, fmaf(c_w[3], x1, c_w[11])));
            c = fmaf(f1, c, i1 * g1);
            h = o1 * tanh_fast(c);
            acc = fmaf(h, c_w[12 + e * 3 + 1], acc);

            // ---- step 2 ----
            float i2 = sigmoid_pre(fmaf(c_w[4], h, fmaf(c_w[0], x2, c_w[8])));
            float f2 = sigmoid_pre(fmaf(c_w[5], h, fmaf(c_w[1], x2, c_w[9])));
            float g2 = tanh_fast  (fmaf(c_w[6], h, fmaf(c_w[2], x2, c_w[10])));
            float o2 = sigmoid_pre(fmaf(c_w[7], h, fmaf(c_w[3], x2, c_w[11])));
            c = fmaf(f2, c, i2 * g2);
            h = o2 * tanh_fast(c);
            acc = fmaf(h, c_w[12 + e * 3 + 2], acc);
        }

        out[r] = acc;
    }
}

extern "C" void kernel_launch(void* const* d_in, const int* in_sizes, int n_in,
                              void* d_out, int out_size)
{
    // Inputs: x, w_ih, w_hh, b_ih, b_hh, w_lin, b_lin
    const float* x = (const float*)d_in[0];

    setup_kernel<<<1, 256>>>((const float*)d_in[1], (const float*)d_in[2],
                             (const float*)d_in[3], (const float*)d_in[4],
                             (const float*)d_in[5], (const float*)d_in[6]);

    void* stage_ptr = nullptr;
    cudaGetSymbolAddress(&stage_ptr, g_stage);
    cudaMemcpyToSymbolAsync(c_w, stage_ptr, 31 * sizeof(float), 0,
                            cudaMemcpyDeviceToDevice, 0);

    int nrows = out_size;   // 2,097,152
    lstm_lin_kernel<<<1184, 256>>>(x, (float*)d_out, nrows);
}